// round 13
// baseline (speedup 1.0000x reference)
#include <cuda_runtime.h>
#include <cuda_fp16.h>
#include <cstdint>

// Problem: S=128, I=J=512, CM=256, C=D=32, CZ=128
// opm CTA = 4i x 4j pairs; grid (128 jt, 128 it); 256 threads; 2 CTAs/SM. Pure fp16.
// Phase A: D[128m x 128n], K=128 (Ah·Bh). 8 warps, tile 32x64 (4x2 grid).
// Phase B: Z[128cz x 16p], K=16kt x 64k (Wh·Oh); warp = 16cz x 16p, no reduction.

// ---------------- smem layout (bytes) ----------------
#define A_RES     0                       // 2 A tiles [128][72] fp16 = 36864
#define B_BUF(b)  (36864 + (b) * 18432)   // 2 B tiles [128][72] fp16 (ends 73728)
#define OHI       0          // O [16p][1032k] fp16 = 33024 (overlaps A; sequential)
#define OSTRIDE   2064
#define ZS_OFF    36864      // zs [16p][132] f32 = 33792 (overlaps B; sequential)
#define WO_OFF    73728      // 2 Wo stages [128cz][72k] fp16 = 36864
#define TSTRIDE   144
#define SMEM2     110592
#define K1_SMEM   ((2*32*260 + 16*256) * 4)

// Pre-tiled globals (plain [row][64k] fp16 tiles):
// g_A3: per it (0..127): 2 tiles (s0-63, s64-127) of [128m][64k]
// g_B3: per jt (0..127): 2 tiles (s0-63, s64-127) of [128n][64k]
// g_Wo3: 16 tiles [128cz][64k]
__device__ __align__(256) __half g_A3[128 * 2 * 8192];
__device__ __align__(256) __half g_B3[128 * 2 * 8192];
__device__ __align__(256) __half g_Wo3[16 * 8192];

// ---------------- helpers ----------------
__device__ __forceinline__ uint32_t smem_u32(const void* p) {
    uint32_t a;
    asm("{ .reg .u64 t; cvta.to.shared.u64 t, %1; cvt.u32.u64 %0, t; }" : "=r"(a) : "l"(p));
    return a;
}
__device__ __forceinline__ void cp16(uint32_t smdst, const void* src) {
    asm volatile("cp.async.cg.shared.global [%0], [%1], 16;" :: "r"(smdst), "l"(src));
}
__device__ __forceinline__ void cp_commit() { asm volatile("cp.async.commit_group;"); }
template<int N> __device__ __forceinline__ void cp_wait() {
    asm volatile("cp.async.wait_group %0;" :: "n"(N));
}
__device__ __forceinline__ void ldm_x4(uint32_t* r, uint32_t addr) {
    asm volatile("ldmatrix.sync.aligned.m8n8.x4.shared.b16 {%0,%1,%2,%3}, [%4];"
                 : "=r"(r[0]), "=r"(r[1]), "=r"(r[2]), "=r"(r[3]) : "r"(addr));
}
__device__ __forceinline__ void mma16816(float* d, const uint32_t* a, uint32_t b0, uint32_t b1) {
    asm volatile(
        "mma.sync.aligned.m16n8k16.row.col.f32.f16.f16.f32 "
        "{%0,%1,%2,%3}, {%4,%5,%6,%7}, {%8,%9}, {%0,%1,%2,%3};"
        : "+f"(d[0]), "+f"(d[1]), "+f"(d[2]), "+f"(d[3])
        : "r"(a[0]), "r"(a[1]), "r"(a[2]), "r"(a[3]), "r"(b0), "r"(b1));
}
__device__ __forceinline__ uint32_t packh2(float lo, float hi) {  // lo -> low half
    __half2 h = __floats2half2_rn(lo, hi);
    return *(uint32_t*)&h;
}
// O column swizzle: bijective on [0,2048) byte cols; same fn on store & load.
__device__ __forceinline__ uint32_t oswz(uint32_t col) {
    return col ^ (((col >> 6) & 7u) << 4);
}
// stage contiguous [rows][64] fp16 tile into smem (TSTRIDE-padded rows)
__device__ __forceinline__ void stage_tile(uint32_t smdst, const __half* g,
                                           int rows, int t, int nthr) {
    const char* s = (const char*)g;
    for (int idx = t; idx < rows * 8; idx += nthr) {
        int r = idx >> 3, c = idx & 7;
        cp16(smdst + r * TSTRIDE + c * 16, s + r * 128 + c * 16);
    }
}

// =====================================================================
// Kernel 0: Wo -> fp16 tiled global.
// =====================================================================
__global__ void wo_prep_kernel(const float* __restrict__ Wo) {
    int idx = blockIdx.x * 256 + threadIdx.x;      // 131072
    int cz = idx >> 10, k = idx & 1023;
    int kt = k >> 6, kk = k & 63;
    g_Wo3[kt * 8192 + cz * 64 + kk] = __float2half_rn(Wo[idx]);
}

// =====================================================================
// Kernel 1: LayerNorm + dual projection -> fp16 pre-tiled globals.
// =====================================================================
__global__ __launch_bounds__(256, 2)
void ln_proj_kernel(const float* __restrict__ x,
                    const float* __restrict__ nw,
                    const float* __restrict__ nb,
                    const float* __restrict__ Wa,
                    const float* __restrict__ Wb)
{
    extern __shared__ float sm[];
    float* Wa_s = sm;                 // [32][260]
    float* Wb_s = sm + 32 * 260;
    float* ln_s = sm + 2 * 32 * 260;  // [16][256]

    const int t = threadIdx.x, lane = t & 31, w = t >> 5;

    for (int idx = t; idx < 8192; idx += 256) {
        int c = idx >> 8, m = idx & 255;
        Wa_s[c * 260 + m] = Wa[idx];
        Wb_s[c * 260 + m] = Wb[idx];
    }

    const int r0 = blockIdx.x * 16 + w * 2;
    #pragma unroll
    for (int rr = 0; rr < 2; rr++) {
        const int row = r0 + rr;
        const float* xr = x + (size_t)row * 256;
        float v[8]; float s = 0.f, sq = 0.f;
        #pragma unroll
        for (int h = 0; h < 2; h++) {
            float4 x4 = *(const float4*)(xr + lane * 4 + 128 * h);
            v[h*4+0]=x4.x; v[h*4+1]=x4.y; v[h*4+2]=x4.z; v[h*4+3]=x4.w;
            s  += x4.x + x4.y + x4.z + x4.w;
            sq += x4.x*x4.x + x4.y*x4.y + x4.z*x4.z + x4.w*x4.w;
        }
        #pragma unroll
        for (int o = 16; o > 0; o >>= 1) {
            s  += __shfl_xor_sync(0xffffffffu, s,  o);
            sq += __shfl_xor_sync(0xffffffffu, sq, o);
        }
        float mu  = s * (1.f / 256.f);
        float var = sq * (1.f / 256.f) - mu * mu;
        float rs  = rsqrtf(var + 1e-5f);
        #pragma unroll
        for (int h = 0; h < 2; h++) {
            int m0 = lane * 4 + 128 * h;
            float4 w4 = *(const float4*)(nw + m0);
            float4 b4 = *(const float4*)(nb + m0);
            float* lp = ln_s + (w * 2 + rr) * 256 + m0;
            lp[0] = (v[h*4+0]-mu)*rs*w4.x + b4.x;
            lp[1] = (v[h*4+1]-mu)*rs*w4.y + b4.y;
            lp[2] = (v[h*4+2]-mu)*rs*w4.z + b4.z;
            lp[3] = (v[h*4+3]-mu)*rs*w4.w + b4.w;
        }
    }
    __syncthreads();

    float accA[2] = {0.f, 0.f}, accB[2] = {0.f, 0.f};
    const float* lr0 = ln_s + (w * 2) * 256;
    const float* lr1 = lr0 + 256;
    const float* war = Wa_s + lane * 260;
    const float* wbr = Wb_s + lane * 260;
    #pragma unroll 8
    for (int m4 = 0; m4 < 64; m4++) {
        float4 wa4 = *(const float4*)(war + m4 * 4);
        float4 wb4 = *(const float4*)(wbr + m4 * 4);
        float4 l0  = *(const float4*)(lr0 + m4 * 4);
        float4 l1  = *(const float4*)(lr1 + m4 * 4);
        accA[0] = fmaf(l0.x, wa4.x, accA[0]); accA[0] = fmaf(l0.y, wa4.y, accA[0]);
        accA[0] = fmaf(l0.z, wa4.z, accA[0]); accA[0] = fmaf(l0.w, wa4.w, accA[0]);
        accB[0] = fmaf(l0.x, wb4.x, accB[0]); accB[0] = fmaf(l0.y, wb4.y, accB[0]);
        accB[0] = fmaf(l0.z, wb4.z, accB[0]); accB[0] = fmaf(l0.w, wb4.w, accB[0]);
        accA[1] = fmaf(l1.x, wa4.x, accA[1]); accA[1] = fmaf(l1.y, wa4.y, accA[1]);
        accA[1] = fmaf(l1.z, wa4.z, accA[1]); accA[1] = fmaf(l1.w, wa4.w, accA[1]);
        accB[1] = fmaf(l1.x, wb4.x, accB[1]); accB[1] = fmaf(l1.y, wb4.y, accB[1]);
        accB[1] = fmaf(l1.z, wb4.z, accB[1]); accB[1] = fmaf(l1.w, wb4.w, accB[1]);
    }

    #pragma unroll
    for (int rr = 0; rr < 2; rr++) {
        const int row = r0 + rr;
        __half ah = __float2half_rn(accA[rr]);
        __half bh = __float2half_rn(accB[rr]);
        const int ss = row >> 9, ij = row & 511;
        const int kts = ss >> 6, kk = ss & 63;
        const int tt = ij >> 2, m = (ij & 3) * 32 + lane;
        g_A3[(size_t)(tt * 2 + kts) * 8192 + m * 64 + kk] = ah;
        g_B3[(size_t)(tt * 2 + kts) * 8192 + m * 64 + kk] = bh;
    }
}

// =====================================================================
// Kernel 2: fused OPM + projection, 256 threads, 2 CTAs/SM, pure fp16.
// =====================================================================
__global__ __launch_bounds__(256, 2)
void opm_kernel(const float* __restrict__ bo, float* __restrict__ out)
{
    extern __shared__ char smc[];
    const uint32_t sb = smem_u32(smc);
    const int t = threadIdx.x, lane = t & 31, wid = t >> 5;
    const int jt = blockIdx.x, it = blockIdx.y;

    const __half* Abase = g_A3 + (size_t)(it * 2) * 8192;
    const __half* Bbase = g_B3 + (size_t)(jt * 2) * 8192;

    // ---- prologue. Commits: c0={A0,A1,B0} c1={B1} c2=W0 c3=W1 ----
    stage_tile(sb + A_RES,         Abase,        128, t, 256);
    stage_tile(sb + A_RES + 18432, Abase + 8192, 128, t, 256);
    stage_tile(sb + B_BUF(0),      Bbase,        128, t, 256);
    cp_commit();                                                    // c0
    stage_tile(sb + B_BUF(1),      Bbase + 8192, 128, t, 256);
    cp_commit();                                                    // c1
    stage_tile(sb + WO_OFF,         g_Wo3,        128, t, 256);
    cp_commit();                                                    // c2
    stage_tile(sb + WO_OFF + 18432, g_Wo3 + 8192, 128, t, 256);
    cp_commit();                                                    // c3

    // ---- Phase A: warps 4x2 (wm 0..3, wn 0..1), tile 32m x 64n, kt 0..1 ----
    const int wm = wid & 3, wn = wid >> 2;
    const uint32_t lrow = (uint32_t)(lane & 15) * TSTRIDE;
    const uint32_t lcol = (uint32_t)(lane >> 4) * 16;
    float acc[2][8][4];
    #pragma unroll
    for (int mt = 0; mt < 2; mt++)
        #pragma unroll
        for (int nt = 0; nt < 8; nt++)
            #pragma unroll
            for (int e = 0; e < 4; e++) acc[mt][nt][e] = 0.f;

    #pragma unroll 1
    for (int kt = 0; kt < 2; kt++) {
        // waits audited: kt0: wait<3> (c0 done); kt1: wait<2> (c1 done)
        if (kt == 0) cp_wait<3>(); else cp_wait<2>();
        __syncthreads();
        const uint32_t aB = sb + A_RES + (uint32_t)kt * 18432
                          + (uint32_t)(wm * 32) * TSTRIDE + lrow + lcol;
        const uint32_t bB = sb + B_BUF(kt)
                          + (uint32_t)(wn * 64) * TSTRIDE + lrow + lcol;
        #pragma unroll
        for (int k16 = 0; k16 < 4; k16++) {
            uint32_t A4[2][4], B4[4][4];
            #pragma unroll
            for (int mt = 0; mt < 2; mt++) ldm_x4(A4[mt], aB + mt * 16 * TSTRIDE + k16 * 32);
            #pragma unroll
            for (int bt = 0; bt < 4; bt++) ldm_x4(B4[bt], bB + bt * 16 * TSTRIDE + k16 * 32);
            #pragma unroll
            for (int mt = 0; mt < 2; mt++)
                #pragma unroll
                for (int bt = 0; bt < 4; bt++) {
                    mma16816(acc[mt][bt*2],   A4[mt], B4[bt][0], B4[bt][2]);
                    mma16816(acc[mt][bt*2+1], A4[mt], B4[bt][1], B4[bt][3]);
                }
        }
        __syncthreads();
    }

    // ---- Epilogue: accums -> O smem (fp16, XOR-swizzled cols) ----
    {
        const int m0 = wm * 32, n0 = wn * 64;
        const int mr = lane >> 2, nc = (lane & 3) * 2;
        #pragma unroll
        for (int mt = 0; mt < 2; mt++)
            #pragma unroll
            for (int nt = 0; nt < 8; nt++) {
                #pragma unroll
                for (int h = 0; h < 2; h++) {
                    int m = m0 + mt * 16 + mr + h * 8;
                    int n = n0 + nt * 8 + nc;
                    float f0 = acc[mt][nt][2*h]   * (1.f / 128.f);
                    float f1 = acc[mt][nt][2*h+1] * (1.f / 128.f);
                    uint32_t hv = packh2(f0, f1);
                    int p = (m >> 5) * 4 + (n >> 5);
                    uint32_t col = oswz((uint32_t)(((m & 31) * 32 + (n & 31)) * 2));
                    uint32_t off = (uint32_t)(p * OSTRIDE) + col;
                    asm volatile("st.shared.b32 [%0], %1;" :: "r"(sb + OHI + off), "r"(hv) : "memory");
                }
            }
    }
    __syncthreads();

    // ---- Phase B: 16 kt stages; warp = 16cz x 16p; double-buffered Wo ----
    float z[2][4];
    #pragma unroll
    for (int ni = 0; ni < 2; ni++)
        #pragma unroll
        for (int e = 0; e < 4; e++) z[ni][e] = 0.f;

    const int czt = wid * 16;
    const uint32_t wrow = (uint32_t)(czt + (lane & 15)) * TSTRIDE + lcol;
    const uint32_t orow = (uint32_t)(lane & 15) * OSTRIDE;

    #pragma unroll 1
    for (int q = 0; q < 16; q++) {
        cp_wait<1>();      // uniform commits: stage q landed
        __syncthreads();
        const uint32_t ws = sb + WO_OFF + (q & 1) * 18432;
        #pragma unroll
        for (int k16 = 0; k16 < 4; k16++) {
            uint32_t Wf[4], Of[4];
            ldm_x4(Wf, ws + wrow + k16 * 32);
            const uint32_t ocol = oswz((uint32_t)(q * 128 + k16 * 32)
                                       + (uint32_t)(lane >> 4) * 16);
            ldm_x4(Of, sb + OHI + orow + ocol);
            mma16816(z[0], Wf, Of[0], Of[2]);
            mma16816(z[1], Wf, Of[1], Of[3]);
        }
        __syncthreads();
        if (q + 2 < 16)
            stage_tile(sb + WO_OFF + (q & 1) * 18432, g_Wo3 + (size_t)(q + 2) * 8192,
                       128, t, 256);
        cp_commit();   // uniform group count (maybe empty)
    }

    // ---- zs staging + coalesced writeout ----
    float* zs = (float*)(smc + ZS_OFF);   // [16p][132cz]
    {
        const int mr = lane >> 2, nc = (lane & 3) * 2;
        #pragma unroll
        for (int ni = 0; ni < 2; ni++)
            #pragma unroll
            for (int e = 0; e < 4; e++) {
                int cz = czt + mr + (e >> 1) * 8;
                int pr = ni * 8 + nc + (e & 1);
                zs[pr * 132 + cz] = z[ni][e];
            }
    }
    __syncthreads();
    #pragma unroll
    for (int q = 0; q < 8; q++) {
        int idx = q * 256 + t;
        int pr = idx >> 7, cz = idx & 127;
        out[((it * 4 + (pr >> 2)) * 512 + jt * 4 + (pr & 3)) * 128 + cz]
            = zs[pr * 132 + cz] + bo[cz];
    }
}

extern "C" void kernel_launch(void* const* d_in, const int* in_sizes, int n_in,
                              void* d_out, int out_size) {
    const float* x  = (const float*)d_in[0];
    const float* nw = (const float*)d_in[1];
    const float* nb = (const float*)d_in[2];
    const float* Wa = (const float*)d_in[3];
    const float* Wb = (const float*)d_in[4];
    const float* Wo = (const float*)d_in[5];
    const float* bo = (const float*)d_in[6];
    float* out = (float*)d_out;

    cudaFuncSetAttribute(ln_proj_kernel, cudaFuncAttributeMaxDynamicSharedMemorySize, K1_SMEM);
    cudaFuncSetAttribute(opm_kernel,     cudaFuncAttributeMaxDynamicSharedMemorySize, SMEM2);

    wo_prep_kernel<<<512, 256>>>(Wo);
    ln_proj_kernel<<<65536 / 16, 256, K1_SMEM>>>(x, nw, nb, Wa, Wb);
    opm_kernel<<<dim3(128, 128), 256, SMEM2>>>(bo, out);
}

// round 14
// speedup vs baseline: 1.0195x; 1.0195x over previous
#include <cuda_runtime.h>
#include <cuda_fp16.h>
#include <cstdint>

// Problem: S=128, I=J=512, CM=256, C=D=32, CZ=128
// opm CTA = 4i x 8j pairs; grid (64 jt, 128 it); 512 threads. Pure fp16.
// Phase A: D[128m x 256n], K=128 (Ah·Bh). 16 warps, tile 32x64.
// Phase B: Z[128cz x 32p], K=16kt x 64k (Wh·Oh); 2 groups (kt parity),
//          3-stage Wo ring per group, single named barrier per stage.

// ---------------- smem layout (bytes) ----------------
#define A_RES     0          // 2 resident A tiles: [128][72] fp16 x2 = 36864
#define B_BUF(b)  (36864 + (b) * 36864)   // 2 x [256][72] fp16  (ends 110592)
#define OHI       0          // O hi [32p][1032k] fp16 (overlaps phase-A bufs; sequential)
#define OSTRIDE   2064
#define WO_OFF    110592
#define GBUF_SZ   30720      // per group: 3 stages x 10240 (hi only)
#define STG_SZ    10240
#define WSTR      80         // Wo stage row stride (64B data + 16 pad)
#define TSTRIDE   144
#define SMEM2     172032
#define K1_SMEM   ((2*32*260 + 16*256) * 4)

// Pre-tiled globals (plain [row][64k] fp16 tiles):
// g_A3: per it: 2 tiles (Ah s0-63, Ah s64-127) of [128m][64k]
// g_B3: per jt: 2 tiles (Bh s0-63, Bh s64-127) of [256n][64k]
// g_Wo3: 16 hi tiles [128cz][64k]
__device__ __align__(256) __half g_A3[128 * 2 * 8192];
__device__ __align__(256) __half g_B3[64 * 2 * 16384];
__device__ __align__(256) __half g_Wo3[16 * 8192];

// ---------------- helpers ----------------
__device__ __forceinline__ uint32_t smem_u32(const void* p) {
    uint32_t a;
    asm("{ .reg .u64 t; cvta.to.shared.u64 t, %1; cvt.u32.u64 %0, t; }" : "=r"(a) : "l"(p));
    return a;
}
__device__ __forceinline__ void cp16(uint32_t smdst, const void* src) {
    asm volatile("cp.async.cg.shared.global [%0], [%1], 16;" :: "r"(smdst), "l"(src));
}
__device__ __forceinline__ void cp_commit() { asm volatile("cp.async.commit_group;"); }
template<int N> __device__ __forceinline__ void cp_wait() {
    asm volatile("cp.async.wait_group %0;" :: "n"(N));
}
__device__ __forceinline__ void barx(int id) {
    asm volatile("bar.sync %0, 256;" :: "r"(id) : "memory");
}
__device__ __forceinline__ void ldm_x4(uint32_t* r, uint32_t addr) {
    asm volatile("ldmatrix.sync.aligned.m8n8.x4.shared.b16 {%0,%1,%2,%3}, [%4];"
                 : "=r"(r[0]), "=r"(r[1]), "=r"(r[2]), "=r"(r[3]) : "r"(addr));
}
__device__ __forceinline__ void mma16816(float* d, const uint32_t* a, uint32_t b0, uint32_t b1) {
    asm volatile(
        "mma.sync.aligned.m16n8k16.row.col.f32.f16.f16.f32 "
        "{%0,%1,%2,%3}, {%4,%5,%6,%7}, {%8,%9}, {%0,%1,%2,%3};"
        : "+f"(d[0]), "+f"(d[1]), "+f"(d[2]), "+f"(d[3])
        : "r"(a[0]), "r"(a[1]), "r"(a[2]), "r"(a[3]), "r"(b0), "r"(b1));
}
__device__ __forceinline__ uint32_t packh2(float lo, float hi) {  // lo -> low half
    __half2 h = __floats2half2_rn(lo, hi);
    return *(uint32_t*)&h;
}
// O column swizzle: bijective on [0,2048) byte cols; same fn on store & load.
__device__ __forceinline__ uint32_t oswz(uint32_t col) {
    return col ^ (((col >> 6) & 7u) << 4);
}
// stage contiguous [rows][64] fp16 tile into smem (TSTRIDE-padded rows)
__device__ __forceinline__ void stage_tile(uint32_t smdst, const __half* g,
                                           int rows, int t, int nthr) {
    const char* s = (const char*)g;
    for (int idx = t; idx < rows * 8; idx += nthr) {
        int r = idx >> 3, c = idx & 7;
        cp16(smdst + r * TSTRIDE + c * 16, s + r * 128 + c * 16);
    }
}
// stage one 32-k hi Wo stage (tile kt, k-half khalf) with 256 threads
__device__ __forceinline__ void stage_w(uint32_t dst, int kt, int khalf, int gt) {
    const char* hi = (const char*)(g_Wo3 + (size_t)kt * 8192) + khalf * 64;
    #pragma unroll
    for (int idx = gt; idx < 512; idx += 256) {
        int r = idx >> 2, c = idx & 3;
        cp16(dst + r * WSTR + c * 16, hi + r * 128 + c * 16);
    }
}

// =====================================================================
// Kernel 0: Wo -> fp16 hi tiled global.
// =====================================================================
__global__ void wo_prep_kernel(const float* __restrict__ Wo) {
    int idx = blockIdx.x * 256 + threadIdx.x;      // 131072
    int cz = idx >> 10, k = idx & 1023;
    int kt = k >> 6, kk = k & 63;
    g_Wo3[kt * 8192 + cz * 64 + kk] = __float2half_rn(Wo[idx]);
}

// =====================================================================
// Kernel 1: LayerNorm + dual projection -> fp16 pre-tiled globals.
// =====================================================================
__global__ __launch_bounds__(256, 2)
void ln_proj_kernel(const float* __restrict__ x,
                    const float* __restrict__ nw,
                    const float* __restrict__ nb,
                    const float* __restrict__ Wa,
                    const float* __restrict__ Wb)
{
    extern __shared__ float sm[];
    float* Wa_s = sm;                 // [32][260]
    float* Wb_s = sm + 32 * 260;
    float* ln_s = sm + 2 * 32 * 260;  // [16][256]

    const int t = threadIdx.x, lane = t & 31, w = t >> 5;

    for (int idx = t; idx < 8192; idx += 256) {
        int c = idx >> 8, m = idx & 255;
        Wa_s[c * 260 + m] = Wa[idx];
        Wb_s[c * 260 + m] = Wb[idx];
    }

    const int r0 = blockIdx.x * 16 + w * 2;
    #pragma unroll
    for (int rr = 0; rr < 2; rr++) {
        const int row = r0 + rr;
        const float* xr = x + (size_t)row * 256;
        float v[8]; float s = 0.f, sq = 0.f;
        #pragma unroll
        for (int h = 0; h < 2; h++) {
            float4 x4 = *(const float4*)(xr + lane * 4 + 128 * h);
            v[h*4+0]=x4.x; v[h*4+1]=x4.y; v[h*4+2]=x4.z; v[h*4+3]=x4.w;
            s  += x4.x + x4.y + x4.z + x4.w;
            sq += x4.x*x4.x + x4.y*x4.y + x4.z*x4.z + x4.w*x4.w;
        }
        #pragma unroll
        for (int o = 16; o > 0; o >>= 1) {
            s  += __shfl_xor_sync(0xffffffffu, s,  o);
            sq += __shfl_xor_sync(0xffffffffu, sq, o);
        }
        float mu  = s * (1.f / 256.f);
        float var = sq * (1.f / 256.f) - mu * mu;
        float rs  = rsqrtf(var + 1e-5f);
        #pragma unroll
        for (int h = 0; h < 2; h++) {
            int m0 = lane * 4 + 128 * h;
            float4 w4 = *(const float4*)(nw + m0);
            float4 b4 = *(const float4*)(nb + m0);
            float* lp = ln_s + (w * 2 + rr) * 256 + m0;
            lp[0] = (v[h*4+0]-mu)*rs*w4.x + b4.x;
            lp[1] = (v[h*4+1]-mu)*rs*w4.y + b4.y;
            lp[2] = (v[h*4+2]-mu)*rs*w4.z + b4.z;
            lp[3] = (v[h*4+3]-mu)*rs*w4.w + b4.w;
        }
    }
    __syncthreads();

    float accA[2] = {0.f, 0.f}, accB[2] = {0.f, 0.f};
    const float* lr0 = ln_s + (w * 2) * 256;
    const float* lr1 = lr0 + 256;
    const float* war = Wa_s + lane * 260;
    const float* wbr = Wb_s + lane * 260;
    #pragma unroll 8
    for (int m4 = 0; m4 < 64; m4++) {
        float4 wa4 = *(const float4*)(war + m4 * 4);
        float4 wb4 = *(const float4*)(wbr + m4 * 4);
        float4 l0  = *(const float4*)(lr0 + m4 * 4);
        float4 l1  = *(const float4*)(lr1 + m4 * 4);
        accA[0] = fmaf(l0.x, wa4.x, accA[0]); accA[0] = fmaf(l0.y, wa4.y, accA[0]);
        accA[0] = fmaf(l0.z, wa4.z, accA[0]); accA[0] = fmaf(l0.w, wa4.w, accA[0]);
        accB[0] = fmaf(l0.x, wb4.x, accB[0]); accB[0] = fmaf(l0.y, wb4.y, accB[0]);
        accB[0] = fmaf(l0.z, wb4.z, accB[0]); accB[0] = fmaf(l0.w, wb4.w, accB[0]);
        accA[1] = fmaf(l1.x, wa4.x, accA[1]); accA[1] = fmaf(l1.y, wa4.y, accA[1]);
        accA[1] = fmaf(l1.z, wa4.z, accA[1]); accA[1] = fmaf(l1.w, wa4.w, accA[1]);
        accB[1] = fmaf(l1.x, wb4.x, accB[1]); accB[1] = fmaf(l1.y, wb4.y, accB[1]);
        accB[1] = fmaf(l1.z, wb4.z, accB[1]); accB[1] = fmaf(l1.w, wb4.w, accB[1]);
    }

    #pragma unroll
    for (int rr = 0; rr < 2; rr++) {
        const int row = r0 + rr;
        __half ah = __float2half_rn(accA[rr]);
        __half bh = __float2half_rn(accB[rr]);
        const int ss = row >> 9, ij = row & 511;
        const int kts = ss >> 6, kk = ss & 63;
        {   // A: Ah at tile kts
            int it = ij >> 2, m = (ij & 3) * 32 + lane;
            g_A3[(size_t)(it * 2 + kts) * 8192 + m * 64 + kk] = ah;
        }
        {   // B: Bh at tile kts
            int jt = ij >> 3, n = (ij & 7) * 32 + lane;
            g_B3[(size_t)(jt * 2 + kts) * 16384 + n * 64 + kk] = bh;
        }
    }
}

// =====================================================================
// Kernel 2: fused OPM + projection, 512 threads, pure fp16.
// =====================================================================
__global__ __launch_bounds__(512, 1)
void opm_kernel(const float* __restrict__ bo, float* __restrict__ out)
{
    extern __shared__ char smc[];
    const uint32_t sb = smem_u32(smc);
    const int t = threadIdx.x, lane = t & 31, wid = t >> 5;
    const int jt = blockIdx.x, it = blockIdx.y;
    const int g  = wid >> 3;              // phase-B group (kt parity)
    const int gt = t & 255;

    const __half* Abase = g_A3 + (size_t)(it * 2) * 8192;
    const __half* Bbase = g_B3 + (size_t)(jt * 2) * 16384;

    // ---- prologue. Commits: c0={A0,B0} c1={A1,B1} c2=Wst0 c3=Wst1 ----
    stage_tile(sb + A_RES,         Abase,         128, t, 512);
    stage_tile(sb + B_BUF(0),      Bbase,         256, t, 512);
    cp_commit();                                                    // c0
    stage_tile(sb + A_RES + 18432, Abase + 8192,  128, t, 512);
    stage_tile(sb + B_BUF(1),      Bbase + 16384, 256, t, 512);
    cp_commit();                                                    // c1
    {   // group g: stage q=0 (kt=g, k0-31) -> buf0, q=1 (kt=g, k32-63) -> buf1
        uint32_t WB = sb + WO_OFF + g * GBUF_SZ;
        stage_w(WB,          g, 0, gt);  cp_commit();               // c2
        stage_w(WB + STG_SZ, g, 1, gt);  cp_commit();               // c3
    }

    // ---- Phase A: kt 0..1, A tile kt, B tile kt ----
    const int wm = wid & 3, wn = wid >> 2;
    const uint32_t lrow = (uint32_t)(lane & 15) * TSTRIDE;
    const uint32_t lcol = (uint32_t)(lane >> 4) * 16;
    float acc[2][8][4];
    #pragma unroll
    for (int mt = 0; mt < 2; mt++)
        #pragma unroll
        for (int nt = 0; nt < 8; nt++)
            #pragma unroll
            for (int e = 0; e < 4; e++) acc[mt][nt][e] = 0.f;

    #pragma unroll 1
    for (int kt = 0; kt < 2; kt++) {
        // waits audited: kt0: wait<3> (c0 done); kt1: wait<2> (c1 done)
        if (kt == 0) cp_wait<3>(); else cp_wait<2>();
        __syncthreads();
        const uint32_t aB = sb + A_RES + (uint32_t)kt * 18432
                          + (uint32_t)(wm * 32) * TSTRIDE + lrow + lcol;
        const uint32_t bB = sb + B_BUF(kt)
                          + (uint32_t)(wn * 64) * TSTRIDE + lrow + lcol;
        #pragma unroll
        for (int k16 = 0; k16 < 4; k16++) {
            uint32_t A4[2][4], B4[4][4];
            #pragma unroll
            for (int mt = 0; mt < 2; mt++) ldm_x4(A4[mt], aB + mt * 16 * TSTRIDE + k16 * 32);
            #pragma unroll
            for (int bt = 0; bt < 4; bt++) ldm_x4(B4[bt], bB + bt * 16 * TSTRIDE + k16 * 32);
            #pragma unroll
            for (int mt = 0; mt < 2; mt++)
                #pragma unroll
                for (int bt = 0; bt < 4; bt++) {
                    mma16816(acc[mt][bt*2],   A4[mt], B4[bt][0], B4[bt][2]);
                    mma16816(acc[mt][bt*2+1], A4[mt], B4[bt][1], B4[bt][3]);
                }
        }
        __syncthreads();
    }

    // ---- Epilogue: accums -> O hi smem (fp16, XOR-swizzled cols) ----
    {
        const int m0 = wm * 32, n0 = wn * 64;
        const int mr = lane >> 2, nc = (lane & 3) * 2;
        #pragma unroll
        for (int mt = 0; mt < 2; mt++)
            #pragma unroll
            for (int nt = 0; nt < 8; nt++) {
                #pragma unroll
                for (int h = 0; h < 2; h++) {
                    int m = m0 + mt * 16 + mr + h * 8;
                    int n = n0 + nt * 8 + nc;
                    float f0 = acc[mt][nt][2*h]   * (1.f / 128.f);
                    float f1 = acc[mt][nt][2*h+1] * (1.f / 128.f);
                    uint32_t hv = packh2(f0, f1);
                    int p = (m >> 5) * 8 + (n >> 5);
                    uint32_t col = oswz((uint32_t)(((m & 31) * 32 + (n & 31)) * 2));
                    uint32_t off = (uint32_t)(p * OSTRIDE) + col;
                    asm volatile("st.shared.b32 [%0], %1;" :: "r"(sb + OHI + off), "r"(hv) : "memory");
                }
            }
    }
    __syncthreads();

    // ---- Phase B: group g, stage q: kt = g+2*(q>>1), k-half = q&1.
    //      3-stage ring (buf = q%3), prefetch distance 2, ONE barx per stage. ----
    float z[4][4];
    #pragma unroll
    for (int nt = 0; nt < 4; nt++)
        #pragma unroll
        for (int e = 0; e < 4; e++) z[nt][e] = 0.f;

    const int wg  = wid & 7;
    const int czt = wg * 16;
    const uint32_t WB   = sb + WO_OFF + g * GBUF_SZ;
    const uint32_t wrow = (uint32_t)(czt + (lane & 15)) * WSTR + (uint32_t)(lane >> 4) * 16;
    const uint32_t orow = (uint32_t)(lane & 15) * OSTRIDE;

    int buf = 0, pbuf = 2;   // buf = q%3; pbuf = (q+2)%3
    #pragma unroll 1
    for (int q = 0; q < 16; q++) {
        const int kt = g + ((q >> 1) << 1);
        const int kh = q & 1;
        cp_wait<1>();       // uniform commits: stage q landed
        barx(1 + g);        // all group warps done reading stage q-1's buffer
        const uint32_t ws = WB + (uint32_t)buf * STG_SZ;
        #pragma unroll
        for (int k16 = 0; k16 < 2; k16++) {
            uint32_t Whi[4], OhA[4], OhB[4];
            ldm_x4(Whi, ws + wrow + k16 * 32);
            const uint32_t ocol = oswz((uint32_t)(kt * 128 + kh * 64 + k16 * 32)
                                       + (uint32_t)(lane >> 4) * 16);
            const uint32_t ob = sb + OHI + orow + ocol;
            ldm_x4(OhA, ob);
            ldm_x4(OhB, ob + 16 * OSTRIDE);
            mma16816(z[0], Whi, OhA[0], OhA[2]); mma16816(z[1], Whi, OhA[1], OhA[3]);
            mma16816(z[2], Whi, OhB[0], OhB[2]); mma16816(z[3], Whi, OhB[1], OhB[3]);
        }
        // stage q+2 into (q+2)%3 — distinct from bufs of stages q and q+1; safe
        // because the next iteration's barx bounds warp skew to one stage.
        if (q + 2 < 16) {
            const int q2 = q + 2;
            stage_w(WB + (uint32_t)pbuf * STG_SZ, g + ((q2 >> 1) << 1), q2 & 1, gt);
        }
        cp_commit();    // uniform group count (maybe empty)
        buf  = (buf  == 2) ? 0 : buf + 1;
        pbuf = (pbuf == 2) ? 0 : pbuf + 1;
    }

    // ---- reduce group partials + writeout ----
    __syncthreads();
    float* zs = (float*)(smc + WO_OFF);   // [32][132] floats (reuses group-0 ring)
    {
        const int mr = lane >> 2, nc = (lane & 3) * 2;
        if (g == 1) {
            #pragma unroll
            for (int nt = 0; nt < 4; nt++)
                #pragma unroll
                for (int e = 0; e < 4; e++) {
                    int cz = czt + mr + (e >> 1) * 8;
                    int pr = nt * 8 + nc + (e & 1);
                    zs[pr * 132 + cz] = z[nt][e];
                }
        }
        __syncthreads();
        if (g == 0) {
            #pragma unroll
            for (int nt = 0; nt < 4; nt++)
                #pragma unroll
                for (int e = 0; e < 4; e++) {
                    int cz = czt + mr + (e >> 1) * 8;
                    int pr = nt * 8 + nc + (e & 1);
                    zs[pr * 132 + cz] += z[nt][e];
                }
        }
    }
    __syncthreads();
    #pragma unroll
    for (int q = 0; q < 8; q++) {
        int idx = q * 512 + t;
        int pr = idx >> 7, cz = idx & 127;
        out[((it * 4 + (pr >> 3)) * 512 + jt * 8 + (pr & 7)) * 128 + cz]
            = zs[pr * 132 + cz] + bo[cz];
    }
}

extern "C" void kernel_launch(void* const* d_in, const int* in_sizes, int n_in,
                              void* d_out, int out_size) {
    const float* x  = (const float*)d_in[0];
    const float* nw = (const float*)d_in[1];
    const float* nb = (const float*)d_in[2];
    const float* Wa = (const float*)d_in[3];
    const float* Wb = (const float*)d_in[4];
    const float* Wo = (const float*)d_in[5];
    const float* bo = (const float*)d_in[6];
    float* out = (float*)d_out;

    cudaFuncSetAttribute(ln_proj_kernel, cudaFuncAttributeMaxDynamicSharedMemorySize, K1_SMEM);
    cudaFuncSetAttribute(opm_kernel,     cudaFuncAttributeMaxDynamicSharedMemorySize, SMEM2);

    wo_prep_kernel<<<512, 256>>>(Wo);
    ln_proj_kernel<<<65536 / 16, 256, K1_SMEM>>>(x, nw, nb, Wa, Wb);
    opm_kernel<<<dim3(64, 128), 512, SMEM2>>>(bo, out);
}